// round 12
// baseline (speedup 1.0000x reference)
#include <cuda_runtime.h>
#include <cuda_fp16.h>
#include <cooperative_groups.h>

namespace cg = cooperative_groups;

#define BB 256
#define TT 2048
#define DD 40
#define HH 128
#define CC 35

// A-operand row stride (halves): 528B; 528 mod 128 = 16 -> conflict-free ldmatrix.
#define AK 264
#define KT0 11   // layer0: [x(40)->48 | h1(128)] K=176 ; pre kt 0..2, crit kt 3..10
#define KT1 16   // layer1: [h1(128) | h2(128)]   K=256 ; pre kt 0..7, crit kt 8..15

__device__ int   g_order[BB];
__device__ int   g_slen[BB];
__device__ float g_h2[BB * HH];

// ---------------- mma / ldsm / activations ----------------
__device__ __forceinline__ void mma16816(float* d, const unsigned* a, const unsigned* b) {
    asm volatile(
        "mma.sync.aligned.m16n8k16.row.col.f32.f16.f16.f32 "
        "{%0,%1,%2,%3}, {%4,%5,%6,%7}, {%8,%9}, {%0,%1,%2,%3};\n"
        : "+f"(d[0]), "+f"(d[1]), "+f"(d[2]), "+f"(d[3])
        : "r"(a[0]), "r"(a[1]), "r"(a[2]), "r"(a[3]), "r"(b[0]), "r"(b[1]));
}
__device__ __forceinline__ void ldsmx4(unsigned* a, const __half* p) {
    unsigned addr = (unsigned)__cvta_generic_to_shared(p);
    asm volatile("ldmatrix.sync.aligned.m8n8.x4.shared.b16 {%0,%1,%2,%3}, [%4];"
                 : "=r"(a[0]), "=r"(a[1]), "=r"(a[2]), "=r"(a[3])
                 : "r"(addr));
}
__device__ __forceinline__ float tanha(float x) {
    float y; asm("tanh.approx.f32 %0, %1;" : "=f"(y) : "f"(x)); return y;
}
__device__ __forceinline__ float sigf(float x) { return fmaf(0.5f, tanha(0.5f * x), 0.5f); }

#define CLUSTER_ARRIVE() asm volatile("barrier.cluster.arrive.aligned;" ::: "memory")
#define CLUSTER_WAIT()   asm volatile("barrier.cluster.wait.aligned;"   ::: "memory")

// ---------------- K0: rank-sort lengths (descending, stable) ----------------
__global__ void sort_kernel(const int* __restrict__ length) {
    __shared__ int len[BB];
    int i = threadIdx.x;
    len[i] = length[i];
    __syncthreads();
    int li = len[i];
    int rank = 0;
    for (int j = 0; j < BB; ++j) {
        int lj = len[j];
        rank += (lj > li) || (lj == li && j < i);
    }
    g_order[rank] = i;
    g_slen[rank]  = li;
}

// ---------------- K1: fused 2-layer LSTM ----------------
// 16 clusters of 8 CTAs. Ranks 0-3: layer 0 (lag 0). Ranks 4-7: layer 1 (lag 2).
// Each CTA: M=16 rows, N=128 gate cols, 128 thr = 4 warps x 4 n-tiles (nt == gate).
// Each thread's 4 accumulators hold all 4 gates of one (row,h) cell -> no shuffles.
// h broadcast: DIRECT per-thread remote half2 stores to every consumer rank
// (no staging smem, no per-round __syncthreads; cluster barrier provides all
// intra/inter-CTA ordering). Feed-forward K-half precomputed after the arrive.
__global__ void __cluster_dims__(8, 1, 1) __launch_bounds__(128, 1)
lstm_fused(const float* __restrict__ x,
           const float* __restrict__ Wih0, const float* __restrict__ Whh0,
           const float* __restrict__ bih0, const float* __restrict__ bhh0,
           const float* __restrict__ Wih1, const float* __restrict__ Whh1,
           const float* __restrict__ bih1, const float* __restrict__ bhh1)
{
    cg::cluster_group cl = cg::this_cluster();
    const int rank   = (int)cl.block_rank();
    const bool is_l0 = (rank < 4);
    const int lrank  = rank & 3;
    const int group  = blockIdx.x >> 3;
    const int slotbase = group * 16;
    const int tid  = threadIdx.x;
    const int warp = tid >> 5, lane = tid & 31;

    __shared__ __align__(16) __half A0[2][16][AK];   // layer-0 CTAs use; layout-mirrored in all
    __shared__ __align__(16) __half A1[3][16][AK];   // layer-1 CTAs use
    __shared__ int slenS[16], morder[16];

    const float* Wih = is_l0 ? Wih0 : Wih1;
    const float* Whh = is_l0 ? Whh0 : Whh1;
    const float* bih = is_l0 ? bih0 : bih1;
    const float* bhh = is_l0 ? bhh0 : bhh1;
    const int KX  = is_l0 ? 48 : 128;
    const int DIN = is_l0 ? DD : HH;

    // ---- weights -> register fragments (nt == gate) ----
    unsigned wf[4][16][2];
#pragma unroll
    for (int nt = 0; nt < 4; ++nt) {
        int grow = nt * 128 + lrank * 32 + warp * 8 + (lane >> 2);
        for (int kt = 0; kt < 16; ++kt) {
            if (kt >= (is_l0 ? KT0 : KT1)) break;
#pragma unroll
            for (int f = 0; f < 2; ++f) {
                int k0 = kt * 16 + (lane & 3) * 2 + f * 8;
                int k1 = k0 + 1;
                float v0 = (k0 < KX) ? ((k0 < DIN) ? Wih[grow * DIN + k0] : 0.0f)
                                     : Whh[grow * HH + (k0 - KX)];
                float v1 = (k1 < KX) ? ((k1 < DIN) ? Wih[grow * DIN + k1] : 0.0f)
                                     : Whh[grow * HH + (k1 - KX)];
                __half2 hv = __floats2half2_rn(v0, v1);
                wf[nt][kt][f] = *reinterpret_cast<unsigned*>(&hv);
            }
        }
    }
    // ---- bias -> registers (acc col = gate nt, h = warp*8 + 2*(lane&3)+{0,1}) ----
    float bias0[4], bias1[4];
#pragma unroll
    for (int nt = 0; nt < 4; ++nt) {
        int g = nt * 128 + lrank * 32 + warp * 8 + 2 * (lane & 3);
        bias0[nt] = bih[g] + bhh[g];
        bias1[nt] = bih[g + 1] + bhh[g + 1];
    }
    if (tid < 16) {
        slenS[tid]  = g_slen[slotbase + tid];
        morder[tid] = g_order[slotbase + tid];
    }
    for (int i = tid; i < 2 * 16 * AK; i += 128) ((__half*)A0)[i] = __float2half(0.0f);
    for (int i = tid; i < 3 * 16 * AK; i += 128) ((__half*)A1)[i] = __float2half(0.0f);
    __syncthreads();
    const int maxlen = slenS[0];

    // per-thread cell ownership: rows r0, r0+8; h-cols hj, hj+1 (one half2 pair)
    const int r0  = lane >> 2;
    const int hj  = warp * 8 + 2 * (lane & 3);
    const int slen_a = slenS[r0], slen_b = slenS[r0 + 8];
    float creg[4] = {0.f, 0.f, 0.f, 0.f};   // q: (r0,hj),(r0,hj+1),(r0+8,hj),(r0+8,hj+1)
    float hreg[4] = {0.f, 0.f, 0.f, 0.f};

    // x prefetch: 640 elems = 5 per thread; loaded TWO steps ahead (xvC/xvN)
    const float* px[5];
    int so[5];
    float xvC[5], xvN[5];
    if (is_l0) {
#pragma unroll
        for (int k = 0; k < 5; ++k) {
            int i = tid + k * 128;
            int m = i / DD, d = i - m * DD;
            px[k] = x + (size_t)morder[m] * TT * DD + d;
            so[k] = m * AK + d;
        }
        for (int i = tid; i < 16 * DD; i += 128) {   // x(0) -> buffer 0
            int m = i / DD, d = i - m * DD;
            A0[0][m][d] = __float2half(x[((size_t)morder[m] * TT) * DD + d]);
        }
        if (maxlen > 1) {                            // xvC = x(1)
#pragma unroll
            for (int k = 0; k < 5; ++k) xvC[k] = px[k][DD];
        }
#pragma unroll
        for (int k = 0; k < 5; ++k) px[k] += 2 * DD; // px -> x(2)
    }
    __syncthreads();

    const int lrowoff = (lane & 15);
    const int lcoloff = (lane >> 4) << 3;

    float acc[4][4];

    // pre-loop precompute for round 0 (l0 only: bias + x(0)-part)
    if (is_l0) {
#pragma unroll
        for (int nt = 0; nt < 4; ++nt) {
            acc[nt][0] = bias0[nt]; acc[nt][1] = bias1[nt];
            acc[nt][2] = bias0[nt]; acc[nt][3] = bias1[nt];
        }
        const __half* ar = &A0[0][lrowoff][lcoloff];
#pragma unroll
        for (int kt = 0; kt < 3; ++kt) {
            unsigned a[4];
            ldsmx4(a, ar + kt * 16);
            mma16816(acc[0], a, wf[0][kt]); mma16816(acc[1], a, wf[1][kt]);
            mma16816(acc[2], a, wf[2][kt]); mma16816(acc[3], a, wf[3][kt]);
        }
    }

    CLUSTER_ARRIVE();   // zero-init + buffer0 published

    for (int s = 0; s <= maxlen + 1; ++s) {
        const int p2 = s & 1;
        const int b3 = s % 3;
        const bool compute = is_l0 ? (s < maxlen) : (s >= 2);

        // issue x(s+2) loads before the barrier wait (2-step latency slack)
        if (is_l0 && s + 2 < maxlen) {
#pragma unroll
            for (int k = 0; k < 5; ++k) { xvN[k] = *px[k]; px[k] += DD; }
        }

        CLUSTER_WAIT();   // recurrent operands for this round have landed

        if (compute) {
            // ---- critical (recurrent) MMA: 8 k-tiles ----
            if (is_l0) {
                const __half* ar = &A0[p2][lrowoff][lcoloff];
#pragma unroll
                for (int kt = 3; kt < 11; ++kt) {
                    unsigned a[4];
                    ldsmx4(a, ar + kt * 16);
                    mma16816(acc[0], a, wf[0][kt]); mma16816(acc[1], a, wf[1][kt]);
                    mma16816(acc[2], a, wf[2][kt]); mma16816(acc[3], a, wf[3][kt]);
                }
            } else {
                const __half* ar = &A1[b3][lrowoff][lcoloff];
#pragma unroll
                for (int kt = 8; kt < 16; ++kt) {
                    unsigned a[4];
                    ldsmx4(a, ar + kt * 16);
                    mma16816(acc[0], a, wf[0][kt]); mma16816(acc[1], a, wf[1][kt]);
                    mma16816(acc[2], a, wf[2][kt]); mma16816(acc[3], a, wf[3][kt]);
                }
            }
            // ---- shuffle-free epilogue: all 4 gates of each cell in-thread ----
            const int t_eff = is_l0 ? s : (s - 2);
#pragma unroll
            for (int q = 0; q < 4; ++q) {
                if (t_eff < ((q < 2) ? slen_a : slen_b)) {
                    float gi = sigf(acc[0][q]);
                    float gf = sigf(acc[1][q]);
                    float gg = tanha(acc[2][q]);
                    float go = sigf(acc[3][q]);
                    float cn = gf * creg[q] + gi * gg;
                    creg[q] = cn;
                    hreg[q] = go * tanha(cn);
                }
            }
            // ---- direct per-thread remote broadcast (no staging, no sync) ----
            __half2 ha = __floats2half2_rn(hreg[0], hreg[1]);
            __half2 hb = __floats2half2_rn(hreg[2], hreg[3]);
            unsigned va = *reinterpret_cast<unsigned*>(&ha);
            unsigned vb = *reinterpret_cast<unsigned*>(&hb);
            if (is_l0) {
                const int bn2 = (s + 1) & 1;          // l0-consumer buffer
                const int bh1 = (s + 2) % 3;          // l1-consumer h1 buffer
                __half* pa0 = &A0[bn2][r0][48 + lrank * 32 + hj];
                __half* pb0 = &A0[bn2][r0 + 8][48 + lrank * 32 + hj];
                __half* pa1 = &A1[bh1][r0][lrank * 32 + hj];
                __half* pb1 = &A1[bh1][r0 + 8][lrank * 32 + hj];
#pragma unroll
                for (int rr = 0; rr < 4; ++rr) {
                    *(unsigned*)cl.map_shared_rank((void*)pa0, rr)     = va;
                    *(unsigned*)cl.map_shared_rank((void*)pb0, rr)     = vb;
                    *(unsigned*)cl.map_shared_rank((void*)pa1, rr + 4) = va;
                    *(unsigned*)cl.map_shared_rank((void*)pb1, rr + 4) = vb;
                }
            } else {
                const int bh2 = (s + 1) % 3;          // l1-consumer h2 buffer
                __half* pa1 = &A1[bh2][r0][128 + lrank * 32 + hj];
                __half* pb1 = &A1[bh2][r0 + 8][128 + lrank * 32 + hj];
#pragma unroll
                for (int rr = 0; rr < 4; ++rr) {
                    *(unsigned*)cl.map_shared_rank((void*)pa1, rr + 4) = va;
                    *(unsigned*)cl.map_shared_rank((void*)pb1, rr + 4) = vb;
                }
            }
        }

        // deferred x(s+1) store into own buffer (s+1)&1 x-region (local only;
        // consumer ldsm is beyond the next arrive/wait pair -> ordered)
        if (is_l0 && s + 1 < maxlen) {
            __half* abf = (__half*)A0[p2 ^ 1];
#pragma unroll
            for (int k = 0; k < 5; ++k) abf[so[k]] = __float2half(xvC[k]);
#pragma unroll
            for (int k = 0; k < 5; ++k) xvC[k] = xvN[k];
        }

        CLUSTER_ARRIVE();   // release: h + x writes ordered before consumers' wait

        // ---- precompute next round's feed-forward MMA (off critical path) ----
        if (is_l0) {
            if (s + 1 < maxlen) {
#pragma unroll
                for (int nt = 0; nt < 4; ++nt) {
                    acc[nt][0] = bias0[nt]; acc[nt][1] = bias1[nt];
                    acc[nt][2] = bias0[nt]; acc[nt][3] = bias1[nt];
                }
                const __half* ar = &A0[p2 ^ 1][lrowoff][lcoloff];
#pragma unroll
                for (int kt = 0; kt < 3; ++kt) {
                    unsigned a[4];
                    ldsmx4(a, ar + kt * 16);
                    mma16816(acc[0], a, wf[0][kt]); mma16816(acc[1], a, wf[1][kt]);
                    mma16816(acc[2], a, wf[2][kt]); mma16816(acc[3], a, wf[3][kt]);
                }
            }
        } else {
            if (s + 1 >= 2 && s <= maxlen) {
#pragma unroll
                for (int nt = 0; nt < 4; ++nt) {
                    acc[nt][0] = bias0[nt]; acc[nt][1] = bias1[nt];
                    acc[nt][2] = bias0[nt]; acc[nt][3] = bias1[nt];
                }
                const __half* ar = &A1[(s + 1) % 3][lrowoff][lcoloff];
#pragma unroll
                for (int kt = 0; kt < 8; ++kt) {
                    unsigned a[4];
                    ldsmx4(a, ar + kt * 16);
                    mma16816(acc[0], a, wf[0][kt]); mma16816(acc[1], a, wf[1][kt]);
                    mma16816(acc[2], a, wf[2][kt]); mma16816(acc[3], a, wf[3][kt]);
                }
            }
        }
    }

    CLUSTER_WAIT();   // pair final arrive; peers done writing into my smem

    if (!is_l0) {
        int hb = lrank * 32 + hj;
        g_h2[(slotbase + r0) * HH + hb]         = hreg[0];
        g_h2[(slotbase + r0) * HH + hb + 1]     = hreg[1];
        g_h2[(slotbase + r0 + 8) * HH + hb]     = hreg[2];
        g_h2[(slotbase + r0 + 8) * HH + hb + 1] = hreg[3];
    }
}

// ---------------- K3: LayerNorm + Linear head ----------------
__global__ void head_kernel(const float* __restrict__ lng, const float* __restrict__ lnb,
                            const float* __restrict__ fw, const float* __restrict__ fb,
                            float* __restrict__ out)
{
    int gm = blockIdx.x;
    int tid = threadIdx.x;       // 128 threads
    int bidx = g_order[gm];
    float v = g_h2[gm * HH + tid];
    float s = v, s2 = v * v;
#pragma unroll
    for (int o = 16; o; o >>= 1) {
        s  += __shfl_xor_sync(0xffffffffu, s, o);
        s2 += __shfl_xor_sync(0xffffffffu, s2, o);
    }
    __shared__ float rs[4], rs2[4], hn[HH];
    if ((tid & 31) == 0) { rs[tid >> 5] = s; rs2[tid >> 5] = s2; }
    __syncthreads();
    float mu  = (rs[0] + rs[1] + rs[2] + rs[3]) * (1.0f / HH);
    float var = (rs2[0] + rs2[1] + rs2[2] + rs2[3]) * (1.0f / HH) - mu * mu;
    hn[tid] = (v - mu) * rsqrtf(var + 1e-5f) * lng[tid] + lnb[tid];
    __syncthreads();
    if (tid < CC) {
        float acc = fb[tid];
#pragma unroll 8
        for (int j = 0; j < HH; ++j) acc += fw[tid * HH + j] * hn[j];
        out[bidx * CC + tid] = acc;
    }
}

// ---------------- launch ----------------
extern "C" void kernel_launch(void* const* d_in, const int* in_sizes, int n_in,
                              void* d_out, int out_size)
{
    (void)in_sizes; (void)n_in; (void)out_size;
    const float* x     = (const float*)d_in[0];
    const int*   len   = (const int*)  d_in[1];
    const float* Wih0  = (const float*)d_in[2];
    const float* Whh0  = (const float*)d_in[3];
    const float* bih0  = (const float*)d_in[4];
    const float* bhh0  = (const float*)d_in[5];
    const float* Wih1  = (const float*)d_in[6];
    const float* Whh1  = (const float*)d_in[7];
    const float* bih1  = (const float*)d_in[8];
    const float* bhh1  = (const float*)d_in[9];
    const float* lng   = (const float*)d_in[10];
    const float* lnb   = (const float*)d_in[11];
    const float* fcw   = (const float*)d_in[12];
    const float* fcb   = (const float*)d_in[13];
    float* out = (float*)d_out;

    sort_kernel<<<1, BB>>>(len);
    lstm_fused<<<128, 128>>>(x, Wih0, Whh0, bih0, bhh0, Wih1, Whh1, bih1, bhh1);
    head_kernel<<<BB, 128>>>(lng, lnb, fcw, fcb, out);
}

// round 15
// speedup vs baseline: 1.0446x; 1.0446x over previous
#include <cuda_runtime.h>
#include <cuda_fp16.h>
#include <cooperative_groups.h>

namespace cg = cooperative_groups;

#define BB 256
#define TT 2048
#define DD 40
#define HH 128
#define CC 35

// A0 row stride (halves): 528B; 528 mod 128 = 16 -> conflict-free ldmatrix.
#define AK  264
// A1h/A1c row stride: 136 halves = 272B; 272 mod 128 = 16 -> conflict-free.
#define AKH 136
#define KT0 11   // layer0: [x(40)->48 | h1(128)] K=176 ; pre kt 0..2, crit kt 3..10
#define KT1 16   // layer1: h1 part kt 0..7 (A1h), h2 part kt 8..15 (A1c)

__device__ int   g_order[BB];
__device__ int   g_slen[BB];
__device__ float g_h2[BB * HH];

// ---------------- mma / ldsm / activations ----------------
__device__ __forceinline__ void mma16816(float* d, const unsigned* a, const unsigned* b) {
    asm volatile(
        "mma.sync.aligned.m16n8k16.row.col.f32.f16.f16.f32 "
        "{%0,%1,%2,%3}, {%4,%5,%6,%7}, {%8,%9}, {%0,%1,%2,%3};\n"
        : "+f"(d[0]), "+f"(d[1]), "+f"(d[2]), "+f"(d[3])
        : "r"(a[0]), "r"(a[1]), "r"(a[2]), "r"(a[3]), "r"(b[0]), "r"(b[1]));
}
__device__ __forceinline__ void ldsmx4(unsigned* a, const __half* p) {
    unsigned addr = (unsigned)__cvta_generic_to_shared(p);
    asm volatile("ldmatrix.sync.aligned.m8n8.x4.shared.b16 {%0,%1,%2,%3}, [%4];"
                 : "=r"(a[0]), "=r"(a[1]), "=r"(a[2]), "=r"(a[3])
                 : "r"(addr));
}
__device__ __forceinline__ float tanha(float x) {
    float y; asm("tanh.approx.f32 %0, %1;" : "=f"(y) : "f"(x)); return y;
}
__device__ __forceinline__ float sigf(float x) { return fmaf(0.5f, tanha(0.5f * x), 0.5f); }

#define CLUSTER_ARRIVE() asm volatile("barrier.cluster.arrive.aligned;" ::: "memory")
#define CLUSTER_WAIT()   asm volatile("barrier.cluster.wait.aligned;"   ::: "memory")

// ---------------- K0: rank-sort lengths (descending, stable) ----------------
__global__ void sort_kernel(const int* __restrict__ length) {
    __shared__ int len[BB];
    int i = threadIdx.x;
    len[i] = length[i];
    __syncthreads();
    int li = len[i];
    int rank = 0;
    for (int j = 0; j < BB; ++j) {
        int lj = len[j];
        rank += (lj > li) || (lj == li && j < i);
    }
    g_order[rank] = i;
    g_slen[rank]  = li;
}

// ---------------- K1: fused 2-layer LSTM ----------------
// 16 clusters of 8 CTAs. Ranks 0-3: layer 0 (lag 0). Ranks 4-7: layer 1 (LAG 3).
// Each CTA: M=16 rows, N=128 gate cols, 128 thr = 4 warps x 4 n-tiles (nt == gate).
// Each thread's 4 accumulators hold all 4 gates of one (row,h) cell -> no shuffles.
// CRITICAL sends (before arrive): recurrent operands only (l0->l0 h1, l1->l1 h2).
// SHADOW send (after arrive): l0->l1 h1(s) into 4-deep ring A1h[s&3]; release-
// covered by arrive(s+1), consumed by l1's pre at round s+2 (after wait(s+2)).
// WAR on A1h: next write shadow(s+4) sits behind wait(s+4) <- l1 arrive(s+3),
// which follows pre(s+2). l1 crit(v) computes h2(v-3) = pre(v-1) + A1c[v&1].
__global__ void __cluster_dims__(8, 1, 1) __launch_bounds__(128, 1)
lstm_fused(const float* __restrict__ x,
           const float* __restrict__ Wih0, const float* __restrict__ Whh0,
           const float* __restrict__ bih0, const float* __restrict__ bhh0,
           const float* __restrict__ Wih1, const float* __restrict__ Whh1,
           const float* __restrict__ bih1, const float* __restrict__ bhh1)
{
    cg::cluster_group cl = cg::this_cluster();
    const int rank   = (int)cl.block_rank();
    const bool is_l0 = (rank < 4);
    const int lrank  = rank & 3;
    const int group  = blockIdx.x >> 3;
    const int slotbase = group * 16;
    const int tid  = threadIdx.x;
    const int warp = tid >> 5, lane = tid & 31;

    __shared__ __align__(16) __half A0[2][16][AK];    // l0: [x(48) | h1(128)]
    __shared__ __align__(16) __half A1h[4][16][AKH];  // l1: h1 operand ring (lag-3)
    __shared__ __align__(16) __half A1c[2][16][AKH];  // l1: h2 recurrent ping-pong
    __shared__ __align__(16) __half hstage[16][40];   // 80B row stride: conflict-free
    __shared__ int slenS[16], morder[16];

    const float* Wih = is_l0 ? Wih0 : Wih1;
    const float* Whh = is_l0 ? Whh0 : Whh1;
    const float* bih = is_l0 ? bih0 : bih1;
    const float* bhh = is_l0 ? bhh0 : bhh1;
    const int KX  = is_l0 ? 48 : 128;
    const int DIN = is_l0 ? DD : HH;

    // ---- weights -> register fragments (nt == gate) ----
    unsigned wf[4][16][2];
#pragma unroll
    for (int nt = 0; nt < 4; ++nt) {
        int grow = nt * 128 + lrank * 32 + warp * 8 + (lane >> 2);
        for (int kt = 0; kt < 16; ++kt) {
            if (kt >= (is_l0 ? KT0 : KT1)) break;
#pragma unroll
            for (int f = 0; f < 2; ++f) {
                int k0 = kt * 16 + (lane & 3) * 2 + f * 8;
                int k1 = k0 + 1;
                float v0 = (k0 < KX) ? ((k0 < DIN) ? Wih[grow * DIN + k0] : 0.0f)
                                     : Whh[grow * HH + (k0 - KX)];
                float v1 = (k1 < KX) ? ((k1 < DIN) ? Wih[grow * DIN + k1] : 0.0f)
                                     : Whh[grow * HH + (k1 - KX)];
                __half2 hv = __floats2half2_rn(v0, v1);
                wf[nt][kt][f] = *reinterpret_cast<unsigned*>(&hv);
            }
        }
    }
    // ---- bias -> registers (acc col = gate nt, h = warp*8 + 2*(lane&3)+{0,1}) ----
    float bias0[4], bias1[4];
#pragma unroll
    for (int nt = 0; nt < 4; ++nt) {
        int g = nt * 128 + lrank * 32 + warp * 8 + 2 * (lane & 3);
        bias0[nt] = bih[g] + bhh[g];
        bias1[nt] = bih[g + 1] + bhh[g + 1];
    }
    if (tid < 16) {
        slenS[tid]  = g_slen[slotbase + tid];
        morder[tid] = g_order[slotbase + tid];
    }
    for (int i = tid; i < 2 * 16 * AK;  i += 128) ((__half*)A0)[i]  = __float2half(0.0f);
    for (int i = tid; i < 4 * 16 * AKH; i += 128) ((__half*)A1h)[i] = __float2half(0.0f);
    for (int i = tid; i < 2 * 16 * AKH; i += 128) ((__half*)A1c)[i] = __float2half(0.0f);
    __syncthreads();
    const int maxlen = slenS[0];

    // per-thread cell ownership: rows r0, r0+8; h-cols hj, hj+1 (one half2 pair)
    const int r0  = lane >> 2;
    const int hj  = warp * 8 + 2 * (lane & 3);
    const int slen_a = slenS[r0], slen_b = slenS[r0 + 8];
    float creg[4] = {0.f, 0.f, 0.f, 0.f};   // q: (r0,hj),(r0,hj+1),(r0+8,hj),(r0+8,hj+1)
    float hreg[4] = {0.f, 0.f, 0.f, 0.f};

    // x prefetch: 640 elems = 5 per thread; loaded TWO steps ahead (xvC/xvN)
    const float* px[5];
    int so[5];
    float xvC[5], xvN[5];
    if (is_l0) {
#pragma unroll
        for (int k = 0; k < 5; ++k) {
            int i = tid + k * 128;
            int m = i / DD, d = i - m * DD;
            px[k] = x + (size_t)morder[m] * TT * DD + d;
            so[k] = m * AK + d;
        }
        for (int i = tid; i < 16 * DD; i += 128) {   // x(0) -> buffer 0
            int m = i / DD, d = i - m * DD;
            A0[0][m][d] = __float2half(x[((size_t)morder[m] * TT) * DD + d]);
        }
        if (maxlen > 1) {                            // xvC = x(1)
#pragma unroll
            for (int k = 0; k < 5; ++k) xvC[k] = px[k][DD];
        }
#pragma unroll
        for (int k = 0; k < 5; ++k) px[k] += 2 * DD; // px -> x(2)
    }
    __syncthreads();

    const int lrowoff = (lane & 15);
    const int lcoloff = (lane >> 4) << 3;

    float acc[4][4];

    // pre-loop precompute for round 0 (l0 only: bias + x(0)-part)
    if (is_l0) {
#pragma unroll
        for (int nt = 0; nt < 4; ++nt) {
            acc[nt][0] = bias0[nt]; acc[nt][1] = bias1[nt];
            acc[nt][2] = bias0[nt]; acc[nt][3] = bias1[nt];
        }
        const __half* ar = &A0[0][lrowoff][lcoloff];
#pragma unroll
        for (int kt = 0; kt < 3; ++kt) {
            unsigned a[4];
            ldsmx4(a, ar + kt * 16);
            mma16816(acc[0], a, wf[0][kt]); mma16816(acc[1], a, wf[1][kt]);
            mma16816(acc[2], a, wf[2][kt]); mma16816(acc[3], a, wf[3][kt]);
        }
    }

    CLUSTER_ARRIVE();   // zero-init + buffer0 published

    for (int s = 0; s <= maxlen + 2; ++s) {
        const int p2 = s & 1;
        const bool compute = is_l0 ? (s < maxlen) : (s >= 3);

        // issue x(s+2) loads before the barrier wait (2-step latency slack)
        if (is_l0 && s + 2 < maxlen) {
#pragma unroll
            for (int k = 0; k < 5; ++k) { xvN[k] = *px[k]; px[k] += DD; }
        }

        CLUSTER_WAIT();   // recurrent operands for this round have landed

        if (compute) {
            // ---- critical (recurrent) MMA: 8 k-tiles ----
            if (is_l0) {
                const __half* ar = &A0[p2][lrowoff][lcoloff];
#pragma unroll
                for (int kt = 3; kt < 11; ++kt) {
                    unsigned a[4];
                    ldsmx4(a, ar + kt * 16);
                    mma16816(acc[0], a, wf[0][kt]); mma16816(acc[1], a, wf[1][kt]);
                    mma16816(acc[2], a, wf[2][kt]); mma16816(acc[3], a, wf[3][kt]);
                }
            } else {
                const __half* ar = &A1c[p2][lrowoff][lcoloff];
#pragma unroll
                for (int kt = 8; kt < 16; ++kt) {
                    unsigned a[4];
                    ldsmx4(a, ar + (kt - 8) * 16);
                    mma16816(acc[0], a, wf[0][kt]); mma16816(acc[1], a, wf[1][kt]);
                    mma16816(acc[2], a, wf[2][kt]); mma16816(acc[3], a, wf[3][kt]);
                }
            }
            // ---- shuffle-free epilogue: all 4 gates of each cell in-thread ----
            const int t_eff = is_l0 ? s : (s - 3);
#pragma unroll
            for (int q = 0; q < 4; ++q) {
                if (t_eff < ((q < 2) ? slen_a : slen_b)) {
                    float gi = sigf(acc[0][q]);
                    float gf = sigf(acc[1][q]);
                    float gg = tanha(acc[2][q]);
                    float go = sigf(acc[3][q]);
                    float cn = gf * creg[q] + gi * gg;
                    creg[q] = cn;
                    hreg[q] = go * tanha(cn);
                }
            }
            *reinterpret_cast<__half2*>(&hstage[r0][hj])     = __floats2half2_rn(hreg[0], hreg[1]);
            *reinterpret_cast<__half2*>(&hstage[r0 + 8][hj]) = __floats2half2_rn(hreg[2], hreg[3]);
        }

        // deferred x(s+1) store into own buffer (s+1)&1 x-region (local only)
        if (is_l0 && s + 1 < maxlen) {
            __half* abf = (__half*)A0[p2 ^ 1];
#pragma unroll
            for (int k = 0; k < 5; ++k) abf[so[k]] = __float2half(xvC[k]);
#pragma unroll
            for (int k = 0; k < 5; ++k) xvC[k] = xvN[k];
        }
        __syncthreads();   // hstage complete; this buffer's reads complete

        // ---- CRITICAL DSMEM sends: recurrent operands only ----
        if (compute) {
#pragma unroll
            for (int k2 = 0; k2 < 2; ++k2) {
                int chunk = k2 * 32 + lane;
                int row = chunk >> 2, c4 = chunk & 3;
                uint4 v = *reinterpret_cast<const uint4*>(&hstage[row][c4 * 8]);
                if (is_l0) {   // h1(s) -> l0 peers' next A0 buffer (read at crit s+1)
                    uint4* d0 = (uint4*)cl.map_shared_rank(
                        (void*)&A0[p2 ^ 1][row][48 + lrank * 32 + c4 * 8], warp);
                    *d0 = v;
                } else {       // h2(s-3) -> l1 peers' next A1c buffer (read at crit s+1)
                    uint4* d1 = (uint4*)cl.map_shared_rank(
                        (void*)&A1c[p2 ^ 1][row][lrank * 32 + c4 * 8], warp + 4);
                    *d1 = v;
                }
            }
        }
        CLUSTER_ARRIVE();   // release: recurrent h + x writes ordered

        // ---- SHADOW send: l0 -> l1 h1(s) into A1h[s&3] ----
        // Covered by arrive(s+1); l1 reads it in pre at round s+2 (after
        // wait(s+2)). Next overwrite of this buffer is shadow(s+4), behind
        // wait(s+4) <- l1 arrive(s+3) >= pre(s+2) completion: no WAR.
        if (is_l0 && compute) {
            const int bsh = s & 3;
#pragma unroll
            for (int k2 = 0; k2 < 2; ++k2) {
                int chunk = k2 * 32 + lane;
                int row = chunk >> 2, c4 = chunk & 3;
                uint4 v = *reinterpret_cast<const uint4*>(&hstage[row][c4 * 8]);
                uint4* d1 = (uint4*)cl.map_shared_rank(
                    (void*)&A1h[bsh][row][lrank * 32 + c4 * 8], warp + 4);
                *d1 = v;
            }
        }

        // ---- precompute next round's feed-forward MMA (off critical path) ----
        if (is_l0) {
            if (s + 1 < maxlen) {
#pragma unroll
                for (int nt = 0; nt < 4; ++nt) {
                    acc[nt][0] = bias0[nt]; acc[nt][1] = bias1[nt];
                    acc[nt][2] = bias0[nt]; acc[nt][3] = bias1[nt];
                }
                const __half* ar = &A0[p2 ^ 1][lrowoff][lcoloff];
#pragma unroll
                for (int kt = 0; kt < 3; ++kt) {
                    unsigned a[4];
                    ldsmx4(a, ar + kt * 16);
                    mma16816(acc[0], a, wf[0][kt]); mma16816(acc[1], a, wf[1][kt]);
                    mma16816(acc[2], a, wf[2][kt]); mma16816(acc[3], a, wf[3][kt]);
                }
            }
        } else {
            // pre(s): read h1(s-2) from A1h[(s-2)&3] (shadow-sent at round s-2,
            // release-covered by arrive(s-1) <-> this round's wait). Prepares
            // crit(s+1) computing h2(s-2).
            if (s >= 2 && s <= maxlen + 1) {
#pragma unroll
                for (int nt = 0; nt < 4; ++nt) {
                    acc[nt][0] = bias0[nt]; acc[nt][1] = bias1[nt];
                    acc[nt][2] = bias0[nt]; acc[nt][3] = bias1[nt];
                }
                const __half* ar = &A1h[(s - 2) & 3][lrowoff][lcoloff];
#pragma unroll
                for (int kt = 0; kt < 8; ++kt) {
                    unsigned a[4];
                    ldsmx4(a, ar + kt * 16);
                    mma16816(acc[0], a, wf[0][kt]); mma16816(acc[1], a, wf[1][kt]);
                    mma16816(acc[2], a, wf[2][kt]); mma16816(acc[3], a, wf[3][kt]);
                }
            }
        }
    }

    CLUSTER_WAIT();   // pair final arrive; peers done writing into my smem

    if (!is_l0) {
        int hb = lrank * 32 + hj;
        g_h2[(slotbase + r0) * HH + hb]         = hreg[0];
        g_h2[(slotbase + r0) * HH + hb + 1]     = hreg[1];
        g_h2[(slotbase + r0 + 8) * HH + hb]     = hreg[2];
        g_h2[(slotbase + r0 + 8) * HH + hb + 1] = hreg[3];
    }
}

// ---------------- K3: LayerNorm + Linear head ----------------
__global__ void head_kernel(const float* __restrict__ lng, const float* __restrict__ lnb,
                            const float* __restrict__ fw, const float* __restrict__ fb,
                            float* __restrict__ out)
{
    int gm = blockIdx.x;
    int tid = threadIdx.x;       // 128 threads
    int bidx = g_order[gm];
    float v = g_h2[gm * HH + tid];
    float s = v, s2 = v * v;
#pragma unroll
    for (int o = 16; o; o >>= 1) {
        s  += __shfl_xor_sync(0xffffffffu, s, o);
        s2 += __shfl_xor_sync(0xffffffffu, s2, o);
    }
    __shared__ float rs[4], rs2[4], hn[HH];
    if ((tid & 31) == 0) { rs[tid >> 5] = s; rs2[tid >> 5] = s2; }
    __syncthreads();
    float mu  = (rs[0] + rs[1] + rs[2] + rs[3]) * (1.0f / HH);
    float var = (rs2[0] + rs2[1] + rs2[2] + rs2[3]) * (1.0f / HH) - mu * mu;
    hn[tid] = (v - mu) * rsqrtf(var + 1e-5f) * lng[tid] + lnb[tid];
    __syncthreads();
    if (tid < CC) {
        float acc = fb[tid];
#pragma unroll 8
        for (int j = 0; j < HH; ++j) acc += fw[tid * HH + j] * hn[j];
        out[bidx * CC + tid] = acc;
    }
}

// ---------------- launch ----------------
extern "C" void kernel_launch(void* const* d_in, const int* in_sizes, int n_in,
                              void* d_out, int out_size)
{
    (void)in_sizes; (void)n_in; (void)out_size;
    const float* x     = (const float*)d_in[0];
    const int*   len   = (const int*)  d_in[1];
    const float* Wih0  = (const float*)d_in[2];
    const float* Whh0  = (const float*)d_in[3];
    const float* bih0  = (const float*)d_in[4];
    const float* bhh0  = (const float*)d_in[5];
    const float* Wih1  = (const float*)d_in[6];
    const float* Whh1  = (const float*)d_in[7];
    const float* bih1  = (const float*)d_in[8];
    const float* bhh1  = (const float*)d_in[9];
    const float* lng   = (const float*)d_in[10];
    const float* lnb   = (const float*)d_in[11];
    const float* fcw   = (const float*)d_in[12];
    const float* fcb   = (const float*)d_in[13];
    float* out = (float*)d_out;

    sort_kernel<<<1, BB>>>(len);
    lstm_fused<<<128, 128>>>(x, Wih0, Whh0, bih0, bhh0, Wih1, Whh1, bih1, bhh1);
    head_kernel<<<BB, 128>>>(lng, lnb, fcw, fcb, out);
}